// round 11
// baseline (speedup 1.0000x reference)
#include <cuda_runtime.h>

#define NPOINTS     500000
#define NWAVE       128
#define NOFFSETS    50

#define TPB         128
#define NBLK        1776            // 12 blocks/SM on 148 SMs
#define TILE        288             // >= max per-block count (282), 16B-multiple
#define QUOT        281             // NPOINTS / NBLK
#define REMR        944             // NPOINTS - QUOT*NBLK

#define RB          128             // stage-2 grid
#define TWO_PI      6.283185307179586f

// Accum-native layout [block][wave].
__device__ float g_partialC[NBLK * NWAVE];
__device__ float g_partialS[NBLK * NWAVE];
// Stage-2 output [RB][wave].
__device__ float g2C[RB * NWAVE];
__device__ float g2S[RB * NWAVE];

__global__ __launch_bounds__(TPB, 12)
void accum_kernel(const float2* __restrict__ xy,
                  const float*  __restrict__ tid,
                  const float*  __restrict__ center,
                  const float*  __restrict__ wavelength)
{
    __shared__ float sdist[TILE];

    const int w  = threadIdx.x;
    const float kw = TWO_PI / wavelength[w];
    const float cx = center[0];
    const float cy = center[1];

    // Balanced contiguous range: blocks differ by at most 1 point of work.
    const int b    = blockIdx.x;
    const int base = b * QUOT + min(b, REMR);
    const int n    = QUOT + (b < REMR ? 1 : 0);     // 281 or 282

    // Phase A: cooperatively compute dist for all of this block's points.
    for (int k = threadIdx.x; k < n; k += TPB) {
        const float2 v = xy[base + k];
        const float dx = v.x - cx;
        const float dy = v.y - cy;
        sdist[k] = sqrtf(fmaf(dx, dx, dy * dy));
    }
    __syncthreads();                                 // the only barrier

    // Phase B: sweep all points for this thread's wavelength.
    const float* __restrict__ trow = tid + (size_t)base * NWAVE + w;
    const float4* __restrict__ sdist4 = (const float4*)sdist;

    float accC = 0.0f;
    float accS = 0.0f;

    const int n4 = n >> 2;
    #pragma unroll 2
    for (int j = 0; j < n4; j++) {
        const float4 d4 = sdist4[j];                 // 1 LDS.128 per 4 points
        const size_t i0 = (size_t)(4 * j) * NWAVE;
        const float t0 = __ldcs(trow + i0);
        const float t1 = __ldcs(trow + i0 + NWAVE);
        const float t2 = __ldcs(trow + i0 + 2 * NWAVE);
        const float t3 = __ldcs(trow + i0 + 3 * NWAVE);

        float s, c;
        __sincosf(d4.x * kw, &s, &c); accC = fmaf(c, t0, accC); accS = fmaf(s, t0, accS);
        __sincosf(d4.y * kw, &s, &c); accC = fmaf(c, t1, accC); accS = fmaf(s, t1, accS);
        __sincosf(d4.z * kw, &s, &c); accC = fmaf(c, t2, accC); accS = fmaf(s, t2, accS);
        __sincosf(d4.w * kw, &s, &c); accC = fmaf(c, t3, accC); accS = fmaf(s, t3, accS);
    }
    for (int i = 4 * n4; i < n; i++) {               // 1-2 remainder points
        const float t = __ldcs(trow + (size_t)i * NWAVE);
        float s, c;
        __sincosf(sdist[i] * kw, &s, &c);
        accC = fmaf(c, t, accC);
        accS = fmaf(s, t, accS);
    }

    g_partialC[b * NWAVE + w] = accC;    // coalesced row store
    g_partialS[b * NWAVE + w] = accS;
}

// Stage 2: plain kernel, no atomics. Mapping (w = t&127, g = t>>7): a warp's
// lanes span 32 consecutive wavelengths of one row -> fully coalesced
// against [block][wave].
__global__ __launch_bounds__(256)
void reduce1_kernel()
{
    __shared__ float smC[2][NWAVE];
    __shared__ float smS[2][NWAVE];

    const int w = threadIdx.x & (NWAVE - 1);
    const int g = threadIdx.x >> 7;

    float c = 0.0f, s = 0.0f;
    #pragma unroll 7
    for (int b = blockIdx.x * 2 + g; b < NBLK; b += RB * 2) {  // fixed order
        c += g_partialC[b * NWAVE + w];
        s += g_partialS[b * NWAVE + w];
    }
    smC[g][w] = c;
    smS[g][w] = s;
    __syncthreads();

    if (g == 0) {
        g2C[blockIdx.x * NWAVE + w] = smC[0][w] + smC[1][w];   // coalesced
        g2S[blockIdx.x * NWAVE + w] = smS[0][w] + smS[1][w];
    }
}

// Stage 3: single block, 256 threads (2 groups of 128), each group sums 64
// L2-hot rows; combine, offset-max epilogue, tree-sum, negate.
__global__ __launch_bounds__(256)
void reduce2_kernel(float* __restrict__ out)
{
    __shared__ float smC[2][NWAVE];
    __shared__ float smS[2][NWAVE];
    __shared__ float smM[NWAVE];

    const int w = threadIdx.x & (NWAVE - 1);
    const int g = threadIdx.x >> 7;

    float c = 0.0f, s = 0.0f;
    #pragma unroll 8
    for (int r = g; r < RB; r += 2) {            // 64 coalesced loads each
        c += g2C[r * NWAVE + w];
        s += g2S[r * NWAVE + w];
    }
    smC[g][w] = c;
    smS[g][w] = s;
    __syncthreads();

    if (g == 0) {
        const float C = (smC[0][w] + smC[1][w]) * (1.0f / (float)NPOINTS);
        const float S = (smS[0][w] + smS[1][w]) * (1.0f / (float)NPOINTS);

        float m = -3.402823466e38f;
        #pragma unroll
        for (int i = 0; i < NOFFSETS; i++) {
            const float o = (float)i * (TWO_PI / (float)(NOFFSETS - 1));
            const float v = C * cosf(o) - S * sinf(o);
            m = fmaxf(m, v);
        }
        smM[w] = m;
    }
    __syncthreads();

    #pragma unroll
    for (int stride = NWAVE / 2; stride > 0; stride >>= 1) {
        if (threadIdx.x < stride) smM[threadIdx.x] += smM[threadIdx.x + stride];
        __syncthreads();
    }
    if (threadIdx.x == 0) out[0] = -smM[0];
}

extern "C" void kernel_launch(void* const* d_in, const int* in_sizes, int n_in,
                              void* d_out, int out_size)
{
    const float2* xy         = (const float2*)d_in[0];  // [500000, 2]
    const float*  tid        = (const float*) d_in[1];  // [500000, 128]
    const float*  center     = (const float*) d_in[2];  // [2]
    const float*  wavelength = (const float*) d_in[3];  // [128]
    float* out = (float*)d_out;

    accum_kernel<<<NBLK, TPB>>>(xy, tid, center, wavelength);
    reduce1_kernel<<<RB, 256>>>();
    reduce2_kernel<<<1, 256>>>(out);
}

// round 12
// speedup vs baseline: 1.0457x; 1.0457x over previous
#include <cuda_runtime.h>
#include <cstdint>

#define NPOINTS     500000
#define NWAVE       128
#define NOFFSETS    50

#define TPB         128
#define NBLK        1776            // 12 blocks/SM on 148 SMs
#define TILE        288             // sdist capacity >= 282
#define QUOT        281             // NPOINTS / NBLK
#define REMR        944             // NPOINTS - QUOT*NBLK

#define SPTS        16              // points per pipeline stage
#define STBYTES     (SPTS * NWAVE * 4)   // 8192 B per stage

#define TWO_PI      6.283185307179586f

// Accum-native layout [block][wave].
__device__ float g_partialC[NBLK * NWAVE];
__device__ float g_partialS[NBLK * NWAVE];
__device__ float g_m[NWAVE];

__global__ __launch_bounds__(TPB, 12)
void accum_kernel(const float2* __restrict__ xy,
                  const float*  __restrict__ tid,
                  const float*  __restrict__ center,
                  const float*  __restrict__ wavelength)
{
    __shared__ __align__(16) float stile[2][SPTS * NWAVE];  // 16 KB double buffer
    __shared__ float sdist[TILE];

    const int w    = threadIdx.x;
    const int b    = blockIdx.x;
    const int base = b * QUOT + min(b, REMR);
    const int n    = QUOT + (b < REMR ? 1 : 0);   // 281 or 282
    const int nst  = (n + SPTS - 1) / SPTS;       // 18

    const char* __restrict__ gsrc = (const char*)(tid + (size_t)base * NWAVE);

    // Issue one 8KB stage: each thread cp.asyncs 4x16B (cg: L2-only path).
    auto issue = [&](int s, int buf) {
        const uint32_t dbase =
            (uint32_t)__cvta_generic_to_shared(&stile[buf][0]);
        const size_t gb = (size_t)s * STBYTES;
        #pragma unroll
        for (int k = 0; k < 4; k++) {
            const int off = threadIdx.x * 16 + k * 2048;
            const int row = s * SPTS + (off >> 9);          // 512B per point-row
            if (row < n) {
                asm volatile("cp.async.cg.shared.global [%0], [%1], 16;\n"
                             :: "r"(dbase + off), "l"(gsrc + gb + off));
            }
        }
        asm volatile("cp.async.commit_group;\n");
    };

    // Prologue: two stages in flight before any compute.
    issue(0, 0);
    if (nst > 1) issue(1, 1);

    // Overlap: compute dist while stage 0/1 stream in.
    const float kw = TWO_PI / wavelength[w];
    const float cx = center[0];
    const float cy = center[1];
    for (int k = threadIdx.x; k < n; k += TPB) {
        const float2 v = xy[base + k];
        const float dx = v.x - cx;
        const float dy = v.y - cy;
        sdist[k] = sqrtf(fmaf(dx, dx, dy * dy));
    }

    float accC = 0.0f;
    float accS = 0.0f;

    for (int s = 0; s < nst; s++) {
        if (s + 1 < nst)
            asm volatile("cp.async.wait_group 1;\n" ::: "memory");
        else
            asm volatile("cp.async.wait_group 0;\n" ::: "memory");
        __syncthreads();                     // stage s visible (also covers sdist)

        const int cnt = min(SPTS, n - s * SPTS);
        const float* __restrict__ tb = &stile[s & 1][w];
        const float* __restrict__ dp = &sdist[s * SPTS];

        int i = 0;
        #pragma unroll 2
        for (; i + 4 <= cnt; i += 4) {
            const float d0 = dp[i],     d1 = dp[i + 1];
            const float d2 = dp[i + 2], d3 = dp[i + 3];
            const float t0 = tb[(i)     * NWAVE];
            const float t1 = tb[(i + 1) * NWAVE];
            const float t2 = tb[(i + 2) * NWAVE];
            const float t3 = tb[(i + 3) * NWAVE];
            float sn, cs;
            __sincosf(d0 * kw, &sn, &cs); accC = fmaf(cs, t0, accC); accS = fmaf(sn, t0, accS);
            __sincosf(d1 * kw, &sn, &cs); accC = fmaf(cs, t1, accC); accS = fmaf(sn, t1, accS);
            __sincosf(d2 * kw, &sn, &cs); accC = fmaf(cs, t2, accC); accS = fmaf(sn, t2, accS);
            __sincosf(d3 * kw, &sn, &cs); accC = fmaf(cs, t3, accC); accS = fmaf(sn, t3, accS);
        }
        for (; i < cnt; i++) {
            const float t = tb[i * NWAVE];
            float sn, cs;
            __sincosf(dp[i] * kw, &sn, &cs);
            accC = fmaf(cs, t, accC);
            accS = fmaf(sn, t, accS);
        }
        __syncthreads();                     // everyone done with buffer s&1
        if (s + 2 < nst) issue(s + 2, s & 1);
    }

    g_partialC[b * NWAVE + w] = accC;        // coalesced row store
    g_partialS[b * NWAVE + w] = accS;
}

// Tail: EXACT R2 structure (the only tail measured at ~3.6us wall).
__global__ __launch_bounds__(256)
void reduce_kernel()
{
    __shared__ float sc[256];
    __shared__ float ss[256];

    const int w = blockIdx.x;
    const int t = threadIdx.x;

    float c = 0.0f, s = 0.0f;
    for (int bb = t; bb < NBLK; bb += 256) {
        c += g_partialC[bb * NWAVE + w];
        s += g_partialS[bb * NWAVE + w];
    }
    sc[t] = c;
    ss[t] = s;
    __syncthreads();

    #pragma unroll
    for (int stride = 128; stride > 0; stride >>= 1) {
        if (t < stride) { sc[t] += sc[t + stride]; ss[t] += ss[t + stride]; }
        __syncthreads();
    }

    if (t == 0) {
        const float C = sc[0] * (1.0f / (float)NPOINTS);
        const float S = ss[0] * (1.0f / (float)NPOINTS);
        float m = -3.402823466e38f;
        #pragma unroll
        for (int i = 0; i < NOFFSETS; i++) {
            const float o = (float)i * (TWO_PI / (float)(NOFFSETS - 1));
            const float v = C * cosf(o) - S * sinf(o);
            m = fmaxf(m, v);
        }
        g_m[w] = m;
    }
}

__global__ void final_sum_kernel(float* __restrict__ out)
{
    __shared__ float sm[NWAVE];
    const int w = threadIdx.x;
    sm[w] = g_m[w];
    __syncthreads();

    #pragma unroll
    for (int stride = NWAVE / 2; stride > 0; stride >>= 1) {
        if (w < stride) sm[w] += sm[w + stride];
        __syncthreads();
    }
    if (w == 0) out[0] = -sm[0];
}

extern "C" void kernel_launch(void* const* d_in, const int* in_sizes, int n_in,
                              void* d_out, int out_size)
{
    const float2* xy         = (const float2*)d_in[0];  // [500000, 2]
    const float*  tid        = (const float*) d_in[1];  // [500000, 128]
    const float*  center     = (const float*) d_in[2];  // [2]
    const float*  wavelength = (const float*) d_in[3];  // [128]
    float* out = (float*)d_out;

    accum_kernel<<<NBLK, TPB>>>(xy, tid, center, wavelength);
    reduce_kernel<<<NWAVE, 256>>>();
    final_sum_kernel<<<1, NWAVE>>>(out);
}

// round 13
// speedup vs baseline: 1.0524x; 1.0064x over previous
#include <cuda_runtime.h>
#include <cstdint>

#define NPOINTS     500000
#define NWAVE       128
#define NOFFSETS    50

#define TPB         128
#define NBLK        1776            // 12 blocks/SM on 148 SMs
#define TILE        288             // sdist capacity >= 282
#define QUOT        281             // NPOINTS / NBLK
#define REMR        944             // NPOINTS - QUOT*NBLK

#define SPTS        16              // points per pipeline stage
#define STBYTES     (SPTS * NWAVE * 4)   // 8192 B per stage
#define NSTG        18              // ceil(282/16): always 18 stages

#define TWO_PI      6.283185307179586f

// Transposed layout [wave][block]: tail reads contiguous rows (R2's layout).
__device__ float g_partialC[NWAVE * NBLK];
__device__ float g_partialS[NWAVE * NBLK];
__device__ float g_m[NWAVE];

__global__ __launch_bounds__(TPB, 12)
void accum_kernel(const float2* __restrict__ xy,
                  const float*  __restrict__ tid,
                  const float*  __restrict__ center,
                  const float*  __restrict__ wavelength)
{
    __shared__ __align__(16) float stile[2][SPTS * NWAVE];  // 16 KB double buffer
    __shared__ float sdist[TILE];

    const int w    = threadIdx.x;
    const int b    = blockIdx.x;
    const int base = b * QUOT + min(b, REMR);
    const int n    = QUOT + (b < REMR ? 1 : 0);   // 281 or 282

    // Hoisted per-thread bases: hot-path cp.async uses only immediate offsets.
    const char* __restrict__ gthr =
        (const char*)(tid + (size_t)base * NWAVE) + threadIdx.x * 16;
    const uint32_t sb0 = (uint32_t)__cvta_generic_to_shared(&stile[0][0]) + threadIdx.x * 16;
    const uint32_t sb1 = (uint32_t)__cvta_generic_to_shared(&stile[1][0]) + threadIdx.x * 16;

    // Full 8KB stage: 4x16B per thread, no predicates (stages 0..16 are full).
    auto issue_full = [&](int s, int buf) {
        const uint32_t d = buf ? sb1 : sb0;
        const char* g = gthr + (size_t)s * STBYTES;
        #pragma unroll
        for (int k = 0; k < 4; k++) {
            asm volatile("cp.async.cg.shared.global [%0], [%1], 16;\n"
                         :: "r"(d + k * 2048), "l"(g + k * 2048));
        }
        asm volatile("cp.async.commit_group;\n");
    };
    // Last (partial) stage: predicate on point row.
    auto issue_tail = [&](int s, int buf) {
        const uint32_t d = buf ? sb1 : sb0;
        const char* g = gthr + (size_t)s * STBYTES;
        const int trow = threadIdx.x >> 5;               // 512B per point-row
        #pragma unroll
        for (int k = 0; k < 4; k++) {
            if (s * SPTS + trow + 4 * k < n) {
                asm volatile("cp.async.cg.shared.global [%0], [%1], 16;\n"
                             :: "r"(d + k * 2048), "l"(g + k * 2048));
            }
        }
        asm volatile("cp.async.commit_group;\n");
    };

    // Prologue: two stages in flight before any compute.
    issue_full(0, 0);
    issue_full(1, 1);

    // Overlap: compute dist while stages stream in.
    const float kw = TWO_PI / wavelength[w];
    const float cx = center[0];
    const float cy = center[1];
    for (int k = threadIdx.x; k < n; k += TPB) {
        const float2 v = xy[base + k];
        const float dx = v.x - cx;
        const float dy = v.y - cy;
        sdist[k] = sqrtf(fmaf(dx, dx, dy * dy));
    }

    float accC = 0.0f;
    float accS = 0.0f;

    for (int s = 0; s < NSTG; s++) {
        if (s + 1 < NSTG)
            asm volatile("cp.async.wait_group 1;\n" ::: "memory");
        else
            asm volatile("cp.async.wait_group 0;\n" ::: "memory");
        __syncthreads();                     // stage s visible (also covers sdist)

        const int cnt = min(SPTS, n - s * SPTS);
        const float* __restrict__ tb = &stile[s & 1][w];
        const float* __restrict__ dp = &sdist[s * SPTS];

        int i = 0;
        #pragma unroll 2
        for (; i + 4 <= cnt; i += 4) {
            const float d0 = dp[i],     d1 = dp[i + 1];
            const float d2 = dp[i + 2], d3 = dp[i + 3];
            const float t0 = tb[(i)     * NWAVE];
            const float t1 = tb[(i + 1) * NWAVE];
            const float t2 = tb[(i + 2) * NWAVE];
            const float t3 = tb[(i + 3) * NWAVE];
            float sn, cs;
            __sincosf(d0 * kw, &sn, &cs); accC = fmaf(cs, t0, accC); accS = fmaf(sn, t0, accS);
            __sincosf(d1 * kw, &sn, &cs); accC = fmaf(cs, t1, accC); accS = fmaf(sn, t1, accS);
            __sincosf(d2 * kw, &sn, &cs); accC = fmaf(cs, t2, accC); accS = fmaf(sn, t2, accS);
            __sincosf(d3 * kw, &sn, &cs); accC = fmaf(cs, t3, accC); accS = fmaf(sn, t3, accS);
        }
        for (; i < cnt; i++) {
            const float t = tb[i * NWAVE];
            float sn, cs;
            __sincosf(dp[i] * kw, &sn, &cs);
            accC = fmaf(cs, t, accC);
            accS = fmaf(sn, t, accS);
        }
        __syncthreads();                     // everyone done with buffer s&1
        if (s + 2 < NSTG) {
            if (s + 2 == NSTG - 1) issue_tail(s + 2, s & 1);
            else                   issue_full(s + 2, s & 1);
        }
    }

    // Transposed (column) store: scattered but tiny; tail reads contiguous.
    g_partialC[w * NBLK + b] = accC;
    g_partialS[w * NBLK + b] = accS;
}

// Tail: EXACT R2 structure against the [w][NBLK] layout (measured ~3.6us wall).
__global__ __launch_bounds__(256)
void reduce_kernel()
{
    __shared__ float sc[256];
    __shared__ float ss[256];

    const int w = blockIdx.x;
    const int t = threadIdx.x;

    const float* __restrict__ pc = g_partialC + (size_t)w * NBLK;
    const float* __restrict__ ps = g_partialS + (size_t)w * NBLK;

    float c = 0.0f, s = 0.0f;
    for (int bb = t; bb < NBLK; bb += 256) {   // contiguous rows, coalesced
        c += pc[bb];
        s += ps[bb];
    }
    sc[t] = c;
    ss[t] = s;
    __syncthreads();

    #pragma unroll
    for (int stride = 128; stride > 0; stride >>= 1) {
        if (t < stride) { sc[t] += sc[t + stride]; ss[t] += ss[t + stride]; }
        __syncthreads();
    }

    if (t == 0) {
        const float C = sc[0] * (1.0f / (float)NPOINTS);
        const float S = ss[0] * (1.0f / (float)NPOINTS);
        float m = -3.402823466e38f;
        #pragma unroll
        for (int i = 0; i < NOFFSETS; i++) {
            const float o = (float)i * (TWO_PI / (float)(NOFFSETS - 1));
            const float v = C * cosf(o) - S * sinf(o);
            m = fmaxf(m, v);
        }
        g_m[w] = m;
    }
}

__global__ void final_sum_kernel(float* __restrict__ out)
{
    __shared__ float sm[NWAVE];
    const int w = threadIdx.x;
    sm[w] = g_m[w];
    __syncthreads();

    #pragma unroll
    for (int stride = NWAVE / 2; stride > 0; stride >>= 1) {
        if (w < stride) sm[w] += sm[w + stride];
        __syncthreads();
    }
    if (w == 0) out[0] = -sm[0];
}

extern "C" void kernel_launch(void* const* d_in, const int* in_sizes, int n_in,
                              void* d_out, int out_size)
{
    const float2* xy         = (const float2*)d_in[0];  // [500000, 2]
    const float*  tid        = (const float*) d_in[1];  // [500000, 128]
    const float*  center     = (const float*) d_in[2];  // [2]
    const float*  wavelength = (const float*) d_in[3];  // [128]
    float* out = (float*)d_out;

    accum_kernel<<<NBLK, TPB>>>(xy, tid, center, wavelength);
    reduce_kernel<<<NWAVE, 256>>>();
    final_sum_kernel<<<1, NWAVE>>>(out);
}